// round 11
// baseline (speedup 1.0000x reference)
#include <cuda_runtime.h>
#include <cuda_fp16.h>
#include <cstdint>
#include <cstring>

#define FEAT   40
#define EDIM   64
#define ADIM   64
#define NB     9            // n-blocks: 8 for W (64 cols) + 1 for pw column
#define NPAIR  780          // FEAT*(FEAT-1)/2
#define NT     256
#define SUPER_P 256         // pairs per supertile (8 warps x 32)
#define NSUPER  4           // ceil(780/256)
#define XS_STRIDE 68        // padded x row
#define NFRAG  (4 * NB * 32)

// ---------------------------------------------------------------------------
// m16n8k16 fp16 MMA with f32 accumulation (arch-generic, works on sm_100)
// ---------------------------------------------------------------------------
__device__ __forceinline__ void mma_fp16(float d[4],
                                         uint32_t a0, uint32_t a1,
                                         uint32_t a2, uint32_t a3,
                                         uint32_t b0, uint32_t b1) {
    asm volatile(
        "mma.sync.aligned.m16n8k16.row.col.f32.f16.f16.f32 "
        "{%0,%1,%2,%3}, {%4,%5,%6,%7}, {%8,%9}, {%0,%1,%2,%3};"
        : "+f"(d[0]), "+f"(d[1]), "+f"(d[2]), "+f"(d[3])
        : "r"(a0), "r"(a1), "r"(a2), "r"(a3), "r"(b0), "r"(b1));
}

__device__ __forceinline__ uint32_t h2u(__half2 h) {
    uint32_t u;
    memcpy(&u, &h, 4);
    return u;
}

// Precomputed W' fragments (hi+lo interleaved) + pair table, built once.
__device__ uint4 g_Wf[NFRAG];                 // {hi.x, hi.y, lo.x, lo.y}
__device__ unsigned char g_pii[800];          // padded to 16B multiple
__device__ unsigned char g_pjj[800];

__global__ void prep_kernel(const float* __restrict__ W,
                            const float* __restrict__ pw) {
    // W' = [W | pw | 0...]: per (eblk, nblk, lane):
    //   n = 8*nblk + lane/4 ; k0 = 16*eblk + (lane%4)*2
    for (int idx = threadIdx.x; idx < NFRAG; idx += 288) {
        int l    = idx & 31;
        int nblk = (idx >> 5) % NB;
        int eblk = (idx >> 5) / NB;
        int n  = 8 * nblk + (l >> 2);
        int k0 = 16 * eblk + (l & 3) * 2;
        float w00, w01, w10, w11;
        if (n < ADIM) {
            w00 = W[(k0    ) * ADIM + n];
            w01 = W[(k0 + 1) * ADIM + n];
            w10 = W[(k0 + 8) * ADIM + n];
            w11 = W[(k0 + 9) * ADIM + n];
        } else if (n == ADIM) {           // the pw column
            w00 = pw[k0];     w01 = pw[k0 + 1];
            w10 = pw[k0 + 8]; w11 = pw[k0 + 9];
        } else {                           // zero padding cols 65..71
            w00 = w01 = w10 = w11 = 0.f;
        }
        __half2 h0 = __floats2half2_rn(w00, w01);
        __half2 h1 = __floats2half2_rn(w10, w11);
        float2 f0 = __half22float2(h0);
        float2 f1 = __half22float2(h1);
        __half2 l0 = __floats2half2_rn(w00 - f0.x, w01 - f0.y);
        __half2 l1 = __floats2half2_rn(w10 - f1.x, w11 - f1.y);
        g_Wf[idx] = make_uint4(h2u(h0), h2u(h1), h2u(l0), h2u(l1));
    }
    // pair table (triu order)
    if (threadIdx.x < FEAT - 1) {
        int i = threadIdx.x;
        int base = i * (FEAT - 1) - i * (i - 1) / 2;
        for (int j = i + 1; j < FEAT; j++) {
            g_pii[base + j - i - 1] = (unsigned char)i;
            g_pjj[base + j - i - 1] = (unsigned char)j;
        }
    }
}

struct __align__(16) Smem {
    float xs[FEAT * XS_STRIDE];   // 10880
    uint4 Wf[NFRAG];              // 18432  hi+lo interleaved fragments
    float sc[NPAIR];              // 3120  scores
    float sq[NPAIR];              // 3120  q_p = BI_p . pw
    float bs[ADIM];
    float hs[ADIM];
    float redm[8];
    float reds[8];
    float redd[8];
    unsigned char pii[800];
    unsigned char pjj[800];
};

__global__ __launch_bounds__(NT, 2)
void afm_main_kernel(const float* __restrict__ x,
                     const float* __restrict__ bias,
                     const float* __restrict__ h,
                     float* __restrict__ out) {
    extern __shared__ char smem_raw[];
    Smem* s = reinterpret_cast<Smem*>(smem_raw);

    const int b    = blockIdx.x;
    const int tid  = threadIdx.x;
    const int wid  = tid >> 5;
    const int lane = tid & 31;

    // ---------------- Phase 0: pure coalesced staging -------------------
    {
        const float* xb = x + (long)b * FEAT * EDIM;
        for (int idx = tid; idx < FEAT * EDIM; idx += NT) {
            int row = idx >> 6, col = idx & 63;
            s->xs[row * XS_STRIDE + col] = xb[idx];
        }
        const uint4* src = (const uint4*)g_Wf;
        uint4* dst = (uint4*)s->Wf;
        for (int i = tid; i < NFRAG; i += NT) dst[i] = src[i];
        {   // pair tables: 2 x 50 uint4
            const uint4* pi = (const uint4*)g_pii;
            const uint4* pj = (const uint4*)g_pjj;
            uint4* di = (uint4*)s->pii;
            uint4* dj = (uint4*)s->pjj;
            if (tid < 50) di[tid] = pi[tid];
            else if (tid < 100) dj[tid - 50] = pj[tid - 50];
        }
        if (tid < ADIM) { s->bs[tid] = bias[tid]; s->hs[tid] = h[tid]; }
    }
    __syncthreads();

    const int r  = lane >> 2;        // row-within-16 (0..7)
    const int c0 = (lane & 3) * 2;   // col pair base

    // ---------------- Phase 1: A=fp16, W=hi+lo split MMA ----------------
    for (int st = 0; st < NSUPER; st++) {
        const int pbase = st * SUPER_P + wid * 32;
        if (pbase >= NPAIR) continue;

        int prow[4];                  // [mb*2 + (0:r,1:r+8)]
        int ofsI[4], ofsJ[4];
        #pragma unroll
        for (int q = 0; q < 4; q++) {
            int p = pbase + 16 * (q >> 1) + r + 8 * (q & 1);
            prow[q] = p;
            int ii = (p < NPAIR) ? s->pii[p] : 0;
            int jj = (p < NPAIR) ? s->pjj[p] : 0;
            ofsI[q] = ii * XS_STRIDE;
            ofsJ[q] = jj * XS_STRIDE;
        }

        // D accumulators: d[mb][nb][4]; bias for nb<8, zero for the q column
        float d[2][NB][4];
        #pragma unroll
        for (int mb = 0; mb < 2; mb++) {
            #pragma unroll
            for (int ab = 0; ab < 8; ab++) {
                float b0v = s->bs[8 * ab + c0];
                float b1v = s->bs[8 * ab + c0 + 1];
                d[mb][ab][0] = b0v; d[mb][ab][1] = b1v;
                d[mb][ab][2] = b0v; d[mb][ab][3] = b1v;
            }
            d[mb][8][0] = 0.f; d[mb][8][1] = 0.f;
            d[mb][8][2] = 0.f; d[mb][8][3] = 0.f;
        }

        #pragma unroll
        for (int eb = 0; eb < 4; eb++) {
            const int e = 16 * eb + c0;
            // --- A fragments: single fp16, RN from exact f32 products ---
            uint32_t ah[2][4];
            #pragma unroll
            for (int mb = 0; mb < 2; mb++) {
                #pragma unroll
                for (int rr = 0; rr < 2; rr++) {
                    const float* pxi = s->xs + ofsI[mb * 2 + rr];
                    const float* pxj = s->xs + ofsJ[mb * 2 + rr];
                    float2 xa  = *(const float2*)(pxi + e);
                    float2 xb2 = *(const float2*)(pxj + e);
                    float2 xc  = *(const float2*)(pxi + e + 8);
                    float2 xd  = *(const float2*)(pxj + e + 8);
                    ah[mb][rr]     = h2u(__floats2half2_rn(xa.x * xb2.x,
                                                           xa.y * xb2.y));
                    ah[mb][rr + 2] = h2u(__floats2half2_rn(xc.x * xd.x,
                                                           xc.y * xd.y));
                }
            }

            // --- one LDS.128 per fragment: {Whi, Wlo}; 4 MMAs each ---
            #pragma unroll
            for (int ab = 0; ab < NB; ab++) {
                uint4 bf = s->Wf[(eb * NB + ab) * 32 + lane];
                mma_fp16(d[0][ab], ah[0][0], ah[0][1], ah[0][2], ah[0][3],
                         bf.x, bf.y);
                mma_fp16(d[1][ab], ah[1][0], ah[1][1], ah[1][2], ah[1][3],
                         bf.x, bf.y);
                mma_fp16(d[0][ab], ah[0][0], ah[0][1], ah[0][2], ah[0][3],
                         bf.z, bf.w);
                mma_fp16(d[1][ab], ah[1][0], ah[1][1], ah[1][2], ah[1][3],
                         bf.z, bf.w);
            }
        }

        // --- epilogue: relu(z)·h reduce, plus direct q extraction ---
        #pragma unroll
        for (int mb = 0; mb < 2; mb++) {
            float s0 = 0.f, s1 = 0.f;
            #pragma unroll
            for (int ab = 0; ab < 8; ab++) {
                int a = 8 * ab + c0;
                float h0v = s->hs[a], h1v = s->hs[a + 1];
                s0 = fmaf(fmaxf(d[mb][ab][0], 0.f), h0v, s0);
                s0 = fmaf(fmaxf(d[mb][ab][1], 0.f), h1v, s0);
                s1 = fmaf(fmaxf(d[mb][ab][2], 0.f), h0v, s1);
                s1 = fmaf(fmaxf(d[mb][ab][3], 0.f), h1v, s1);
            }
            s0 += __shfl_xor_sync(0xffffffffu, s0, 1);
            s0 += __shfl_xor_sync(0xffffffffu, s0, 2);
            s1 += __shfl_xor_sync(0xffffffffu, s1, 1);
            s1 += __shfl_xor_sync(0xffffffffu, s1, 2);
            if ((lane & 3) == 0) {
                int p0 = prow[mb * 2];
                int p1 = prow[mb * 2 + 1];
                if (p0 < NPAIR) {
                    s->sc[p0] = s0;
                    s->sq[p0] = d[mb][8][0];   // q_p: col 64 lives in lanes c0==0
                }
                if (p1 < NPAIR) {
                    s->sc[p1] = s1;
                    s->sq[p1] = d[mb][8][2];
                }
            }
        }
    }
    __syncthreads();

    // ---------------- Phase 2: fused softmax + weighted dot -------------
    float m = -3.402823466e38f;
    for (int p = tid; p < NPAIR; p += NT) m = fmaxf(m, s->sc[p]);
    #pragma unroll
    for (int o = 16; o; o >>= 1) m = fmaxf(m, __shfl_xor_sync(0xffffffffu, m, o));
    if (lane == 0) s->redm[wid] = m;
    __syncthreads();
    if (tid == 0) {
        float mm = s->redm[0];
        #pragma unroll
        for (int w = 1; w < 8; w++) mm = fmaxf(mm, s->redm[w]);
        s->redm[0] = mm;
    }
    __syncthreads();
    m = s->redm[0];

    float sum = 0.f, dot = 0.f;
    for (int p = tid; p < NPAIR; p += NT) {
        float e0 = __expf(s->sc[p] - m);
        sum += e0;
        dot = fmaf(e0, s->sq[p], dot);
    }
    #pragma unroll
    for (int o = 16; o; o >>= 1) {
        sum += __shfl_xor_sync(0xffffffffu, sum, o);
        dot += __shfl_xor_sync(0xffffffffu, dot, o);
    }
    if (lane == 0) { s->reds[wid] = sum; s->redd[wid] = dot; }
    __syncthreads();
    if (tid == 0) {
        float ss = s->reds[0], dd = s->redd[0];
        #pragma unroll
        for (int w = 1; w < 8; w++) { ss += s->reds[w]; dd += s->redd[w]; }
        out[b] = (float)NPAIR * dd / ss;
    }
}

extern "C" void kernel_launch(void* const* d_in, const int* in_sizes, int n_in,
                              void* d_out, int out_size) {
    const float* x    = (const float*)d_in[0];
    const float* W    = (const float*)d_in[1];
    const float* bias = (const float*)d_in[2];
    const float* h    = (const float*)d_in[3];
    const float* pw   = (const float*)d_in[4];
    float* out = (float*)d_out;

    int B = in_sizes[0] / (FEAT * EDIM);
    size_t smem_bytes = sizeof(Smem);

    static bool attr_set = false;
    if (!attr_set) {
        cudaFuncSetAttribute(afm_main_kernel,
                             cudaFuncAttributeMaxDynamicSharedMemorySize,
                             (int)smem_bytes);
        attr_set = true;
    }

    prep_kernel<<<1, 288>>>(W, pw);
    afm_main_kernel<<<B, NT, smem_bytes>>>(x, bias, h, out);
}

// round 12
// speedup vs baseline: 1.1914x; 1.1914x over previous
#include <cuda_runtime.h>
#include <cuda_fp16.h>
#include <cstdint>
#include <cstring>

#define FEAT   40
#define EDIM   64
#define ADIM   64
#define NB     9            // n-blocks: 8 for W (64 cols) + 1 for pw column
#define NPAIR  780          // FEAT*(FEAT-1)/2
#define NT     256
#define SUPER_P 256         // pairs per supertile (8 warps x 32)
#define NSUPER  4           // ceil(780/256)
#define XS_STRIDE 68        // padded x row
#define NFRAG  (4 * NB * 32)

// ---------------------------------------------------------------------------
// m16n8k16 fp16 MMA with f32 accumulation (arch-generic, works on sm_100)
// ---------------------------------------------------------------------------
__device__ __forceinline__ void mma_fp16(float d[4],
                                         uint32_t a0, uint32_t a1,
                                         uint32_t a2, uint32_t a3,
                                         uint32_t b0, uint32_t b1) {
    asm volatile(
        "mma.sync.aligned.m16n8k16.row.col.f32.f16.f16.f32 "
        "{%0,%1,%2,%3}, {%4,%5,%6,%7}, {%8,%9}, {%0,%1,%2,%3};"
        : "+f"(d[0]), "+f"(d[1]), "+f"(d[2]), "+f"(d[3])
        : "r"(a0), "r"(a1), "r"(a2), "r"(a3), "r"(b0), "r"(b1));
}

__device__ __forceinline__ uint32_t h2u(__half2 h) {
    uint32_t u;
    memcpy(&u, &h, 4);
    return u;
}

// Precomputed W' fragments (single fp16) + pair table, built once.
__device__ uint2 g_Whf[NFRAG];
__device__ unsigned char g_pii[800];          // padded to 16B multiple
__device__ unsigned char g_pjj[800];

__global__ void prep_kernel(const float* __restrict__ W,
                            const float* __restrict__ pw) {
    // W' = [W | pw | 0...]: per (eblk, nblk, lane):
    //   n = 8*nblk + lane/4 ; k0 = 16*eblk + (lane%4)*2
    for (int idx = threadIdx.x; idx < NFRAG; idx += 288) {
        int l    = idx & 31;
        int nblk = (idx >> 5) % NB;
        int eblk = (idx >> 5) / NB;
        int n  = 8 * nblk + (l >> 2);
        int k0 = 16 * eblk + (l & 3) * 2;
        float w00, w01, w10, w11;
        if (n < ADIM) {
            w00 = W[(k0    ) * ADIM + n];
            w01 = W[(k0 + 1) * ADIM + n];
            w10 = W[(k0 + 8) * ADIM + n];
            w11 = W[(k0 + 9) * ADIM + n];
        } else if (n == ADIM) {           // the pw column
            w00 = pw[k0];     w01 = pw[k0 + 1];
            w10 = pw[k0 + 8]; w11 = pw[k0 + 9];
        } else {                           // zero padding cols 65..71
            w00 = w01 = w10 = w11 = 0.f;
        }
        g_Whf[idx] = make_uint2(h2u(__floats2half2_rn(w00, w01)),
                                h2u(__floats2half2_rn(w10, w11)));
    }
    // pair table (triu order)
    if (threadIdx.x < FEAT - 1) {
        int i = threadIdx.x;
        int base = i * (FEAT - 1) - i * (i - 1) / 2;
        for (int j = i + 1; j < FEAT; j++) {
            g_pii[base + j - i - 1] = (unsigned char)i;
            g_pjj[base + j - i - 1] = (unsigned char)j;
        }
    }
}

struct __align__(16) Smem {
    float xs[FEAT * XS_STRIDE];   // 10880
    uint2 Whf[NFRAG];             // 9216  W' fragments [eblk][nblk][lane]
    float sc[NPAIR];              // 3120  scores
    float sq[NPAIR];              // 3120  q_p = BI_p . pw
    float bs[ADIM];
    float hs[ADIM];
    float redm[8];
    float reds[8];
    float redd[8];
    unsigned char pii[800];
    unsigned char pjj[800];
};

__global__ __launch_bounds__(NT, 2)
void afm_main_kernel(const float* __restrict__ x,
                     const float* __restrict__ bias,
                     const float* __restrict__ h,
                     float* __restrict__ out) {
    extern __shared__ char smem_raw[];
    Smem* s = reinterpret_cast<Smem*>(smem_raw);

    const int b    = blockIdx.x;
    const int tid  = threadIdx.x;
    const int wid  = tid >> 5;
    const int lane = tid & 31;

    // ---------------- Phase 0: pure coalesced staging -------------------
    {
        const float* xb = x + (long)b * FEAT * EDIM;
        for (int idx = tid; idx < FEAT * EDIM; idx += NT) {
            int row = idx >> 6, col = idx & 63;
            s->xs[row * XS_STRIDE + col] = xb[idx];
        }
        const uint4* src = (const uint4*)g_Whf;     // 9216 B = 576 uint4
        uint4* dst = (uint4*)s->Whf;
        for (int i = tid; i < 576; i += NT) dst[i] = src[i];
        {   // pair tables: 2 x 50 uint4
            const uint4* pi = (const uint4*)g_pii;
            const uint4* pj = (const uint4*)g_pjj;
            uint4* di = (uint4*)s->pii;
            uint4* dj = (uint4*)s->pjj;
            if (tid < 50) di[tid] = pi[tid];
            else if (tid < 100) dj[tid - 50] = pj[tid - 50];
        }
        if (tid < ADIM) { s->bs[tid] = bias[tid]; s->hs[tid] = h[tid]; }
    }
    __syncthreads();

    const int r  = lane >> 2;        // row-within-16 (0..7)
    const int c0 = (lane & 3) * 2;   // col pair base

    // ---------------- Phase 1: pure fp16 MMA (A and W both fp16) --------
    for (int st = 0; st < NSUPER; st++) {
        const int pbase = st * SUPER_P + wid * 32;
        if (pbase >= NPAIR) continue;

        int prow[4];                  // [mb*2 + (0:r,1:r+8)]
        int ofsI[4], ofsJ[4];
        #pragma unroll
        for (int q = 0; q < 4; q++) {
            int p = pbase + 16 * (q >> 1) + r + 8 * (q & 1);
            prow[q] = p;
            int ii = (p < NPAIR) ? s->pii[p] : 0;
            int jj = (p < NPAIR) ? s->pjj[p] : 0;
            ofsI[q] = ii * XS_STRIDE;
            ofsJ[q] = jj * XS_STRIDE;
        }

        // D accumulators: d[mb][nb][4]; bias for nb<8, zero for the q column
        float d[2][NB][4];
        #pragma unroll
        for (int mb = 0; mb < 2; mb++) {
            #pragma unroll
            for (int ab = 0; ab < 8; ab++) {
                float b0v = s->bs[8 * ab + c0];
                float b1v = s->bs[8 * ab + c0 + 1];
                d[mb][ab][0] = b0v; d[mb][ab][1] = b1v;
                d[mb][ab][2] = b0v; d[mb][ab][3] = b1v;
            }
            d[mb][8][0] = 0.f; d[mb][8][1] = 0.f;
            d[mb][8][2] = 0.f; d[mb][8][3] = 0.f;
        }

        #pragma unroll
        for (int eb = 0; eb < 4; eb++) {
            const int e = 16 * eb + c0;
            // --- A fragments: single fp16, RN from exact f32 products ---
            uint32_t ah[2][4];
            #pragma unroll
            for (int mb = 0; mb < 2; mb++) {
                #pragma unroll
                for (int rr = 0; rr < 2; rr++) {
                    const float* pxi = s->xs + ofsI[mb * 2 + rr];
                    const float* pxj = s->xs + ofsJ[mb * 2 + rr];
                    float2 xa  = *(const float2*)(pxi + e);
                    float2 xb2 = *(const float2*)(pxj + e);
                    float2 xc  = *(const float2*)(pxi + e + 8);
                    float2 xd  = *(const float2*)(pxj + e + 8);
                    ah[mb][rr]     = h2u(__floats2half2_rn(xa.x * xb2.x,
                                                           xa.y * xb2.y));
                    ah[mb][rr + 2] = h2u(__floats2half2_rn(xc.x * xd.x,
                                                           xc.y * xd.y));
                }
            }

            // --- one LDS.64 per fragment; 2 MMAs each ---
            #pragma unroll
            for (int ab = 0; ab < NB; ab++) {
                uint2 bf = s->Whf[(eb * NB + ab) * 32 + lane];
                mma_fp16(d[0][ab], ah[0][0], ah[0][1], ah[0][2], ah[0][3],
                         bf.x, bf.y);
                mma_fp16(d[1][ab], ah[1][0], ah[1][1], ah[1][2], ah[1][3],
                         bf.x, bf.y);
            }
        }

        // --- epilogue: relu(z)·h reduce, plus direct q extraction ---
        #pragma unroll
        for (int mb = 0; mb < 2; mb++) {
            float s0 = 0.f, s1 = 0.f;
            #pragma unroll
            for (int ab = 0; ab < 8; ab++) {
                int a = 8 * ab + c0;
                float h0v = s->hs[a], h1v = s->hs[a + 1];
                s0 = fmaf(fmaxf(d[mb][ab][0], 0.f), h0v, s0);
                s0 = fmaf(fmaxf(d[mb][ab][1], 0.f), h1v, s0);
                s1 = fmaf(fmaxf(d[mb][ab][2], 0.f), h0v, s1);
                s1 = fmaf(fmaxf(d[mb][ab][3], 0.f), h1v, s1);
            }
            s0 += __shfl_xor_sync(0xffffffffu, s0, 1);
            s0 += __shfl_xor_sync(0xffffffffu, s0, 2);
            s1 += __shfl_xor_sync(0xffffffffu, s1, 1);
            s1 += __shfl_xor_sync(0xffffffffu, s1, 2);
            if ((lane & 3) == 0) {
                int p0 = prow[mb * 2];
                int p1 = prow[mb * 2 + 1];
                if (p0 < NPAIR) {
                    s->sc[p0] = s0;
                    s->sq[p0] = d[mb][8][0];   // q_p: col 64 lives in lanes c0==0
                }
                if (p1 < NPAIR) {
                    s->sc[p1] = s1;
                    s->sq[p1] = d[mb][8][2];
                }
            }
        }
    }
    __syncthreads();

    // ---------------- Phase 2: fused softmax + weighted dot -------------
    float m = -3.402823466e38f;
    for (int p = tid; p < NPAIR; p += NT) m = fmaxf(m, s->sc[p]);
    #pragma unroll
    for (int o = 16; o; o >>= 1) m = fmaxf(m, __shfl_xor_sync(0xffffffffu, m, o));
    if (lane == 0) s->redm[wid] = m;
    __syncthreads();
    if (tid == 0) {
        float mm = s->redm[0];
        #pragma unroll
        for (int w = 1; w < 8; w++) mm = fmaxf(mm, s->redm[w]);
        s->redm[0] = mm;
    }
    __syncthreads();
    m = s->redm[0];

    float sum = 0.f, dot = 0.f;
    for (int p = tid; p < NPAIR; p += NT) {
        float e0 = __expf(s->sc[p] - m);
        sum += e0;
        dot = fmaf(e0, s->sq[p], dot);
    }
    #pragma unroll
    for (int o = 16; o; o >>= 1) {
        sum += __shfl_xor_sync(0xffffffffu, sum, o);
        dot += __shfl_xor_sync(0xffffffffu, dot, o);
    }
    if (lane == 0) { s->reds[wid] = sum; s->redd[wid] = dot; }
    __syncthreads();
    if (tid == 0) {
        float ss = s->reds[0], dd = s->redd[0];
        #pragma unroll
        for (int w = 1; w < 8; w++) { ss += s->reds[w]; dd += s->redd[w]; }
        out[b] = (float)NPAIR * dd / ss;
    }
}

extern "C" void kernel_launch(void* const* d_in, const int* in_sizes, int n_in,
                              void* d_out, int out_size) {
    const float* x    = (const float*)d_in[0];
    const float* W    = (const float*)d_in[1];
    const float* bias = (const float*)d_in[2];
    const float* h    = (const float*)d_in[3];
    const float* pw   = (const float*)d_in[4];
    float* out = (float*)d_out;

    int B = in_sizes[0] / (FEAT * EDIM);
    size_t smem_bytes = sizeof(Smem);

    static bool attr_set = false;
    if (!attr_set) {
        cudaFuncSetAttribute(afm_main_kernel,
                             cudaFuncAttributeMaxDynamicSharedMemorySize,
                             (int)smem_bytes);
        attr_set = true;
    }

    prep_kernel<<<1, 288>>>(W, pw);
    afm_main_kernel<<<B, NT, smem_bytes>>>(x, bias, h, out);
}